// round 13
// baseline (speedup 1.0000x reference)
#include <cuda_runtime.h>
#include <cuda_bf16.h>
#include <cstdint>

// Problem constants (fixed: source/target are [4096, 256] f32)
#define B_ROWS 4096
#define NROWS  8192
#define D      256
#define TILE   128
#define NT     (NROWS / TILE)          // 64 tiles per side
#define NPAIRS (NT * (NT + 1) / 2)     // 2080 upper-tri tile pairs
#define BK     64                      // K chunk
#define NKC    (D / BK)                // 4 chunks
#define ABYTES (TILE * BK * 2)         // 16384 bytes per operand chunk
#define BUFB   (2 * ABYTES)            // 32768 bytes per pipeline buffer
#define NBUF   3                       // triple-buffer rotation

// ---- device scratch (no allocations allowed; zero-initialized at load) ----
__device__ __align__(16) __nv_bfloat16 g_bf16[NROWS * D];  // 4 MB converted inputs
__device__ float    g_sq[NROWS];
__device__ float    g_colsum[D];
__device__ double   g_sumsq;
__device__ double   g_acc;

// ---------------------------------------------------------------------------
// PTX helpers (baseline PTX only -- compiles for compute_103)
// ---------------------------------------------------------------------------
__device__ __forceinline__ float ex2f(float x) {
    float y; asm("ex2.approx.ftz.f32 %0, %1;" : "=f"(y) : "f"(x)); return y;
}
__device__ __forceinline__ uint32_t smem_u32(const void* p) {
    uint32_t a;
    asm("{ .reg .u64 t; cvta.to.shared.u64 t, %1; cvt.u32.u64 %0, t; }"
        : "=r"(a) : "l"(p));
    return a;
}
__device__ __forceinline__ void cpasync16(uint32_t dst, const void* src) {
    asm volatile("cp.async.cg.shared.global [%0], [%1], 16;"
                 :: "r"(dst), "l"(src) : "memory");
}
#define CP_COMMIT() asm volatile("cp.async.commit_group;" ::: "memory")
#define CP_WAIT(n)  asm volatile("cp.async.wait_group %0;" :: "n"(n) : "memory")

#define LDSM4(r, addr) \
    asm volatile("ldmatrix.sync.aligned.m8n8.x4.shared.b16 {%0,%1,%2,%3}, [%4];" \
                 : "=r"((r)[0]), "=r"((r)[1]), "=r"((r)[2]), "=r"((r)[3]) \
                 : "r"(addr))

#define MMA16816(d, a, b0, b1) \
    asm volatile("mma.sync.aligned.m16n8k16.row.col.f32.bf16.bf16.f32 " \
                 "{%0,%1,%2,%3}, {%4,%5,%6,%7}, {%8,%9}, {%0,%1,%2,%3};" \
                 : "+f"((d)[0]), "+f"((d)[1]), "+f"((d)[2]), "+f"((d)[3]) \
                 : "r"((a)[0]), "r"((a)[1]), "r"((a)[2]), "r"((a)[3]), \
                   "r"(b0), "r"(b1))

// L2-coherent loads (read values produced by another kernel's atomics)
__device__ __forceinline__ float ldcg_f(const float* p) {
    float v; asm volatile("ld.global.cg.f32 %0, [%1];" : "=f"(v) : "l"(p)); return v;
}
__device__ __forceinline__ double ldcg_d(const double* p) {
    double v; asm volatile("ld.global.cg.f64 %0, [%1];" : "=d"(v) : "l"(p)); return v;
}

// ---- packed f32x2 (PTX ISA 8.6, base sm_100 family -- register-only ops) ----
__device__ __forceinline__ uint64_t pk2(float lo, float hi) {
    uint64_t r; asm("mov.b64 %0, {%1, %2};" : "=l"(r) : "f"(lo), "f"(hi)); return r;
}
__device__ __forceinline__ void upk2(float& lo, float& hi, uint64_t v) {
    asm("mov.b64 {%0, %1}, %2;" : "=f"(lo), "=f"(hi) : "l"(v));
}
__device__ __forceinline__ uint64_t fma2p(uint64_t a, uint64_t b, uint64_t c) {
    uint64_t d; asm("fma.rn.f32x2 %0, %1, %2, %3;" : "=l"(d) : "l"(a), "l"(b), "l"(c)); return d;
}
__device__ __forceinline__ uint64_t mul2p(uint64_t a, uint64_t b) {
    uint64_t d; asm("mul.rn.f32x2 %0, %1, %2;" : "=l"(d) : "l"(a), "l"(b)); return d;
}
__device__ __forceinline__ uint64_t add2p(uint64_t a, uint64_t b) {
    uint64_t d; asm("add.rn.f32x2 %0, %1, %2;" : "=l"(d) : "l"(a), "l"(b)); return d;
}

// ---------------------------------------------------------------------------
// k_prep: f32 -> bf16 conversion + row sq-norms + column sums.
// 256 blocks x 256 threads; warp w owns rows blockIdx.x*32 + w*4 + {0..3};
// lane l owns 8 contiguous cols. NO ticket / NO fence: the bandwidth constant
// is computed redundantly by every k_mma CTA (kernel-launch ordering makes
// the atomics visible), and k_fin resets the accumulators for replays.
// ---------------------------------------------------------------------------
__global__ void k_prep(const float* __restrict__ src, const float* __restrict__ tgt) {
    __shared__ __align__(16) float scol[8][D];   // per-warp column partials (8 KB)
    __shared__ float swsq[32];
    const int t = threadIdx.x, w = t >> 5, l = t & 31;
    const int r0 = blockIdx.x * 32 + w * 4;

    // front-batched loads: 8 independent LDG.128 (cols 8l..8l+7 of 4 rows)
    float4 a[4], b[4];
    #pragma unroll
    for (int j = 0; j < 4; j++) {
        int row = r0 + j;
        const float* p = (row < B_ROWS) ? src + (size_t)row * D
                                        : tgt + (size_t)(row - B_ROWS) * D;
        a[j] = *(const float4*)(p + l * 8);
        b[j] = *(const float4*)(p + l * 8 + 4);
    }

    float cs[8] = {0.f, 0.f, 0.f, 0.f, 0.f, 0.f, 0.f, 0.f};
    #pragma unroll
    for (int j = 0; j < 4; j++) {
        int row = r0 + j;
        __nv_bfloat162 h0 = __floats2bfloat162_rn(a[j].x, a[j].y);
        __nv_bfloat162 h1 = __floats2bfloat162_rn(a[j].z, a[j].w);
        __nv_bfloat162 h2 = __floats2bfloat162_rn(b[j].x, b[j].y);
        __nv_bfloat162 h3 = __floats2bfloat162_rn(b[j].z, b[j].w);
        uint4 v;
        v.x = *(const uint32_t*)&h0; v.y = *(const uint32_t*)&h1;
        v.z = *(const uint32_t*)&h2; v.w = *(const uint32_t*)&h3;
        *(uint4*)(g_bf16 + (size_t)row * D + l * 8) = v;

        cs[0] += a[j].x; cs[1] += a[j].y; cs[2] += a[j].z; cs[3] += a[j].w;
        cs[4] += b[j].x; cs[5] += b[j].y; cs[6] += b[j].z; cs[7] += b[j].w;

        float sq = a[j].x * a[j].x + a[j].y * a[j].y + a[j].z * a[j].z + a[j].w * a[j].w
                 + b[j].x * b[j].x + b[j].y * b[j].y + b[j].z * b[j].z + b[j].w * b[j].w;
        #pragma unroll
        for (int k = 16; k; k >>= 1) sq += __shfl_xor_sync(0xFFFFFFFFu, sq, k);
        if (l == 0) { g_sq[row] = sq; swsq[w * 4 + j] = sq; }
    }

    *(float4*)&scol[w][l * 8]     = make_float4(cs[0], cs[1], cs[2], cs[3]);
    *(float4*)&scol[w][l * 8 + 4] = make_float4(cs[4], cs[5], cs[6], cs[7]);
    __syncthreads();

    float c = 0.f;
    #pragma unroll
    for (int i = 0; i < 8; i++) c += scol[i][t];
    atomicAdd(&g_colsum[t], c);
    if (t == 0) {
        double bs = 0.0;
        #pragma unroll
        for (int i = 0; i < 32; i++) bs += (double)swsq[i];
        atomicAdd(&g_sumsq, bs);
    }
}

// ---------------------------------------------------------------------------
// k_mma: one upper-tri 128x128 tile pair per CTA.
//   Proven rolling mainloop + triple-buffer rotation (one sync per chunk).
//   Each CTA redundantly computes the bandwidth constant c2 from
//   g_colsum/g_sumsq: warp-level partials before the loop (hidden under the
//   stage(0) cp.async flight), thread 0 combines after the kc=0 barrier,
//   the kc=1 barrier publishes s_c2 -- two barriers before the epilogue.
//   bf16 mma.sync, fp32 accum, packed-f32x2 exp epilogue, shuffle reduce,
//   one atomicAdd per CTA. 8 warps, warp tile = 32 (M) x 64 (N).
// ---------------------------------------------------------------------------
extern __shared__ char dynsmem[];

__global__ void __launch_bounds__(256, 2) k_mma() {
    __shared__ float  s_sqi[TILE];
    __shared__ float  s_sqj[TILE];
    __shared__ double s_csp[8];     // per-warp colsum^2 partials
    __shared__ float  s_c2[1];
    __shared__ double sp8[8];

    const int t = threadIdx.x;
    const int w = t >> 5, l = t & 31;

    // decode upper-tri pair (I <= J)
    int I = 0, rem = blockIdx.x;
    while (rem >= NT - I) { rem -= NT - I; I++; }
    const int J = I + rem;

    const __nv_bfloat16* Abase = g_bf16 + (size_t)I * TILE * D;
    const __nv_bfloat16* Bbase = g_bf16 + (size_t)J * TILE * D;
    const uint32_t sdyn = smem_u32(dynsmem);

    // ---- cp.async staging: 2048 x 16B chunks per K-chunk ----
    auto stage = [&](int kc, int buf) {
        #pragma unroll
        for (int i = 0; i < 8; i++) {
            int idx = t + i * 256;
            int op  = idx >> 10;
            int li  = idx & 1023;
            int row = li >> 3;
            int ch  = li & 7;
            const __nv_bfloat16* gp =
                (op ? Bbase : Abase) + (size_t)row * D + kc * BK + ch * 8;
            uint32_t dst = sdyn + (uint32_t)buf * BUFB + (uint32_t)op * ABYTES
                         + (uint32_t)(row * 128 + (((ch ^ (row & 7)) << 4)));
            cpasync16(dst, gp);
        }
        CP_COMMIT();
    };

    stage(0, 0);   // issue first chunk ASAP; c2 prep below overlaps its flight

    // raw sq-norm tiles (c2 applied in the epilogue)
    if (t < TILE) {
        s_sqi[t] = ldcg_f(&g_sq[I * TILE + t]);
        s_sqj[t] = ldcg_f(&g_sq[J * TILE + t]);
    }
    // per-warp colsum^2 partials in double (warp w owns colsum[w*32 + l])
    {
        double cc = (double)ldcg_f(&g_colsum[w * 32 + l]);
        double d = cc * cc;
        #pragma unroll
        for (int k = 16; k; k >>= 1) d += __shfl_xor_sync(0xFFFFFFFFu, d, k);
        if (l == 0) s_csp[w] = d;
    }
    double ssq = 0.0;
    if (t == 0) ssq = ldcg_d(&g_sumsq);

    // ---- per-lane ldmatrix base offsets ----
    const int wm = (w >> 1) * 32;    // warp M offset (0,32,64,96)
    const int wn = (w & 1) * 64;     // warp N offset (0,64)
    const uint32_t xr   = (uint32_t)((l & 7) << 4);        // swizzle XOR
    const uint32_t arow = (uint32_t)(wm + (l & 15));
    const uint32_t khA  = (uint32_t)(l >> 4);
    const uint32_t brow = (uint32_t)(wn + (l & 7) + ((l & 16) ? 8 : 0));
    const uint32_t khB  = (uint32_t)((l >> 3) & 1);

    float acc[2][8][4];
    #pragma unroll
    for (int mi = 0; mi < 2; mi++)
        #pragma unroll
        for (int ni = 0; ni < 8; ni++)
            #pragma unroll
            for (int c = 0; c < 4; c++) acc[mi][ni][c] = 0.f;

    auto compute = [&](int buf) {
        const uint32_t bo = (uint32_t)buf * BUFB;
        const uint32_t aB = sdyn + bo + arow * 128u;
        const uint32_t bB = sdyn + bo + ABYTES + brow * 128u;
        #pragma unroll
        for (int kk = 0; kk < 4; kk++) {
            uint32_t ka = ((uint32_t)(kk * 32) + khA * 16u) ^ xr;
            uint32_t kb = ((uint32_t)(kk * 32) + khB * 16u) ^ xr;
            uint32_t af[2][4], bf[4][4];
            LDSM4(af[0], aB + ka);
            LDSM4(af[1], aB + 2048u + ka);
            LDSM4(bf[0], bB + kb);
            LDSM4(bf[1], bB + 2048u + kb);
            LDSM4(bf[2], bB + 4096u + kb);
            LDSM4(bf[3], bB + 6144u + kb);
            #pragma unroll
            for (int mi = 0; mi < 2; mi++)
                #pragma unroll
                for (int nj = 0; nj < 4; nj++) {
                    MMA16816(acc[mi][nj * 2 + 0], af[mi], bf[nj][0], bf[nj][1]);
                    MMA16816(acc[mi][nj * 2 + 1], af[mi], bf[nj][2], bf[nj][3]);
                }
        }
    };

    #pragma unroll 1
    for (int kc = 0; kc < NKC; kc++) {
        int nb = kc + 1;  if (nb >= NBUF) nb -= NBUF;   // (kc+1)%3
        if (kc + 1 < NKC) stage(kc + 1, nb);
        if (kc + 1 < NKC) { CP_WAIT(1); } else { CP_WAIT(0); }
        __syncthreads();
        if (kc == 0 && t == 0) {
            // combine partials -> c2 (published by the kc=1 barrier)
            double colsq = 0.0;
            #pragma unroll
            for (int i = 0; i < 8; i++) colsq += s_csp[i];
            double n = (double)NROWS;
            double sumL2 = 2.0 * n * ssq - 2.0 * colsq;
            double bw = sumL2 / (n * n - n) * 0.25;   // / 2^(KERNEL_NUM//2)
            s_c2[0] = (float)(-1.0 / (16.0 * bw * 0.6931471805599453094));
        }
        int cb = kc;      if (cb >= NBUF) cb -= NBUF;   // kc%3
        compute(cb);
        // no trailing sync: next stage targets a buffer whose readers all
        // passed the previous iteration's barrier
    }

    // ---- fused epilogue ----
    // element (mi,ni,c): m = wm + mi*16 + gr + (c>=2)*8 ; n = wn + ni*8 + gc + (c&1)
    const float c2   = s_c2[0];          // published by the kc=1 barrier
    const int gr = l >> 2;
    const int gc = (l & 3) * 2;
    const float m2c2 = -2.0f * c2;
    const bool diag = (I == J);

    float facc = 0.f;
    if (!diag) {
        const uint64_t m2c2p = pk2(m2c2, m2c2);
        uint64_t rbp[2][2];
        #pragma unroll
        for (int mi = 0; mi < 2; mi++)
            #pragma unroll
            for (int rh = 0; rh < 2; rh++) {
                float rv = c2 * s_sqi[wm + mi * 16 + rh * 8 + gr];
                rbp[mi][rh] = pk2(rv, rv);
            }
        uint64_t cvp[8];
        #pragma unroll
        for (int ni = 0; ni < 8; ni++) {
            float c0 = c2 * s_sqj[wn + ni * 8 + gc];
            float c1 = c2 * s_sqj[wn + ni * 8 + gc + 1];
            cvp[ni] = pk2(c0, c1);
        }
        uint64_t faccp = pk2(0.f, 0.f);
        #pragma unroll
        for (int mi = 0; mi < 2; mi++)
            #pragma unroll
            for (int ni = 0; ni < 8; ni++)
                #pragma unroll
                for (int rh = 0; rh < 2; rh++) {
                    uint64_t accp = pk2(acc[mi][ni][rh * 2], acc[mi][ni][rh * 2 + 1]);
                    uint64_t argp = fma2p(accp, m2c2p, add2p(rbp[mi][rh], cvp[ni]));
                    float a0, a1; upk2(a0, a1, argp);
                    uint64_t u  = pk2(ex2f(a0), ex2f(a1));
                    uint64_t u2 = mul2p(u, u), u4 = mul2p(u2, u2);
                    uint64_t u8 = mul2p(u4, u4), u16 = mul2p(u8, u8);
                    uint64_t s  = add2p(add2p(u, u2), add2p(u4, u8));
                    faccp = add2p(faccp, add2p(s, u16));
                }
        float f0, f1; upk2(f0, f1, faccp);
        facc = f0 + f1;
    } else {
        float rb[2][2];
        #pragma unroll
        for (int mi = 0; mi < 2; mi++)
            #pragma unroll
            for (int rh = 0; rh < 2; rh++)
                rb[mi][rh] = c2 * s_sqi[wm + mi * 16 + rh * 8 + gr];
        #pragma unroll
        for (int mi = 0; mi < 2; mi++)
            #pragma unroll
            for (int ni = 0; ni < 8; ni++)
                #pragma unroll
                for (int c = 0; c < 4; c++) {
                    int rh = c >> 1, cc = c & 1;
                    int mm = wm + mi * 16 + rh * 8 + gr;
                    int nn = wn + ni * 8 + gc + cc;
                    float arg = fmaf(acc[mi][ni][c], m2c2,
                                     fmaf(c2, s_sqj[nn], rb[mi][rh]));
                    float u = ex2f(arg);
                    float u2 = u * u, u4 = u2 * u2, u8 = u4 * u4, u16 = u8 * u8;
                    float kv = ((u + u2) + (u4 + u8)) + u16;
                    facc += (nn > mm) ? kv : 0.f;   // strict upper triangle
                }
    }

    // block reduction: warp shuffle in double, 8 partials, one atomic
    const double sg = ((I < NT / 2) == (J < NT / 2)) ? 1.0 : -1.0;
    double dv = (double)facc * sg;
    #pragma unroll
    for (int k = 16; k; k >>= 1) dv += __shfl_xor_sync(0xFFFFFFFFu, dv, k);
    if (l == 0) sp8[w] = dv;
    __syncthreads();
    if (t == 0) {
        double s = 0.0;
        #pragma unroll
        for (int i = 0; i < 8; i++) s += sp8[i];
        atomicAdd(&g_acc, s);
    }
}

// ---------------------------------------------------------------------------
// k_fin: result = (2*sum_{i<j} + 5*n) / b^2 (diagonal K_ii = 5 exactly);
// resets ALL accumulators for the next graph replay (prep is reset-free now).
// ---------------------------------------------------------------------------
__global__ void k_fin(float* out) {
    int t = threadIdx.x;
    if (t == 0) {
        out[0] = (float)((2.0 * g_acc + 5.0 * (double)NROWS)
                         / ((double)B_ROWS * (double)B_ROWS));
        g_acc = 0.0;
        g_sumsq = 0.0;
    }
    g_colsum[t] = 0.f;
}

extern "C" void kernel_launch(void* const* d_in, const int* in_sizes, int n_in,
                              void* d_out, int out_size) {
    const float* src = (const float*)d_in[0];
    const float* tgt = (const float*)d_in[1];
    float* out = (float*)d_out;

    static const int kDynSmem = NBUF * BUFB;   // 96 KB triple-buffer rotation
    cudaFuncSetAttribute(k_mma, cudaFuncAttributeMaxDynamicSharedMemorySize, kDynSmem);

    k_prep<<<NROWS / 32, 256>>>(src, tgt);
    k_mma<<<NPAIRS, 256, kDynSmem>>>();
    k_fin<<<1, 256>>>(out);
}

// round 14
// speedup vs baseline: 1.0902x; 1.0902x over previous
#include <cuda_runtime.h>
#include <cuda_bf16.h>
#include <cstdint>

// Problem constants (fixed: source/target are [4096, 256] f32)
#define B_ROWS 4096
#define NROWS  8192
#define D      256
#define TILE   128
#define NT     (NROWS / TILE)          // 64 tiles per side
#define NPAIRS (NT * (NT + 1) / 2)     // 2080 upper-tri tile pairs
#define BK     64                      // K chunk
#define NKC    (D / BK)                // 4 chunks
#define ABYTES (TILE * BK * 2)         // 16384 bytes per operand chunk
#define BUFB   (2 * ABYTES)            // 32768 bytes per pipeline buffer
#define NBUF   3                       // triple-buffer rotation

// ---- device scratch (no allocations allowed; zero-initialized at load) ----
__device__ __align__(16) __nv_bfloat16 g_bf16[NROWS * D];  // 4 MB converted inputs
__device__ float    g_sq[NROWS];
__device__ float    g_colsum[D];
__device__ double   g_sumsq;
__device__ double   g_acc;
__device__ float    g_c2;     // u = exp2(c2 * L2) = exp(-L2/(16*bw))

// ---------------------------------------------------------------------------
// PTX helpers (baseline PTX only -- compiles for compute_103)
// ---------------------------------------------------------------------------
__device__ __forceinline__ float ex2f(float x) {
    float y; asm("ex2.approx.ftz.f32 %0, %1;" : "=f"(y) : "f"(x)); return y;
}
__device__ __forceinline__ uint32_t smem_u32(const void* p) {
    uint32_t a;
    asm("{ .reg .u64 t; cvta.to.shared.u64 t, %1; cvt.u32.u64 %0, t; }"
        : "=r"(a) : "l"(p));
    return a;
}
__device__ __forceinline__ void cpasync16(uint32_t dst, const void* src) {
    asm volatile("cp.async.cg.shared.global [%0], [%1], 16;"
                 :: "r"(dst), "l"(src) : "memory");
}
#define CP_COMMIT() asm volatile("cp.async.commit_group;" ::: "memory")
#define CP_WAIT(n)  asm volatile("cp.async.wait_group %0;" :: "n"(n) : "memory")

#define LDSM4(r, addr) \
    asm volatile("ldmatrix.sync.aligned.m8n8.x4.shared.b16 {%0,%1,%2,%3}, [%4];" \
                 : "=r"((r)[0]), "=r"((r)[1]), "=r"((r)[2]), "=r"((r)[3]) \
                 : "r"(addr))

#define MMA16816(d, a, b0, b1) \
    asm volatile("mma.sync.aligned.m16n8k16.row.col.f32.bf16.bf16.f32 " \
                 "{%0,%1,%2,%3}, {%4,%5,%6,%7}, {%8,%9}, {%0,%1,%2,%3};" \
                 : "+f"((d)[0]), "+f"((d)[1]), "+f"((d)[2]), "+f"((d)[3]) \
                 : "r"((a)[0]), "r"((a)[1]), "r"((a)[2]), "r"((a)[3]), \
                   "r"(b0), "r"(b1))

// L2-coherent loads (read values produced by another kernel's atomics)
__device__ __forceinline__ float ldcg_f(const float* p) {
    float v; asm volatile("ld.global.cg.f32 %0, [%1];" : "=f"(v) : "l"(p)); return v;
}
__device__ __forceinline__ double ldcg_d(const double* p) {
    double v; asm volatile("ld.global.cg.f64 %0, [%1];" : "=d"(v) : "l"(p)); return v;
}

// ---- packed f32x2 (PTX ISA 8.6, base sm_100 family -- register-only ops) ----
__device__ __forceinline__ uint64_t pk2(float lo, float hi) {
    uint64_t r; asm("mov.b64 %0, {%1, %2};" : "=l"(r) : "f"(lo), "f"(hi)); return r;
}
__device__ __forceinline__ void upk2(float& lo, float& hi, uint64_t v) {
    asm("mov.b64 {%0, %1}, %2;" : "=f"(lo), "=f"(hi) : "l"(v));
}
__device__ __forceinline__ uint64_t fma2p(uint64_t a, uint64_t b, uint64_t c) {
    uint64_t d; asm("fma.rn.f32x2 %0, %1, %2, %3;" : "=l"(d) : "l"(a), "l"(b), "l"(c)); return d;
}
__device__ __forceinline__ uint64_t mul2p(uint64_t a, uint64_t b) {
    uint64_t d; asm("mul.rn.f32x2 %0, %1, %2;" : "=l"(d) : "l"(a), "l"(b)); return d;
}
__device__ __forceinline__ uint64_t add2p(uint64_t a, uint64_t b) {
    uint64_t d; asm("add.rn.f32x2 %0, %1, %2;" : "=l"(d) : "l"(a), "l"(b)); return d;
}

// ---------------------------------------------------------------------------
// k_prep: f32 -> bf16 conversion + row sq-norms + column sums.
// 256 blocks x 256 threads; warp w owns rows blockIdx.x*32 + w*4 + {0..3};
// lane l owns 8 contiguous cols. Lean: no fence / no ticket (k_bw runs as a
// separate launch; kernel ordering makes the atomics visible).
// ---------------------------------------------------------------------------
__global__ void k_prep(const float* __restrict__ src, const float* __restrict__ tgt) {
    __shared__ __align__(16) float scol[8][D];   // per-warp column partials (8 KB)
    __shared__ float swsq[32];
    const int t = threadIdx.x, w = t >> 5, l = t & 31;
    const int r0 = blockIdx.x * 32 + w * 4;

    // front-batched loads: 8 independent LDG.128 (cols 8l..8l+7 of 4 rows)
    float4 a[4], b[4];
    #pragma unroll
    for (int j = 0; j < 4; j++) {
        int row = r0 + j;
        const float* p = (row < B_ROWS) ? src + (size_t)row * D
                                        : tgt + (size_t)(row - B_ROWS) * D;
        a[j] = *(const float4*)(p + l * 8);
        b[j] = *(const float4*)(p + l * 8 + 4);
    }

    float cs[8] = {0.f, 0.f, 0.f, 0.f, 0.f, 0.f, 0.f, 0.f};
    #pragma unroll
    for (int j = 0; j < 4; j++) {
        int row = r0 + j;
        __nv_bfloat162 h0 = __floats2bfloat162_rn(a[j].x, a[j].y);
        __nv_bfloat162 h1 = __floats2bfloat162_rn(a[j].z, a[j].w);
        __nv_bfloat162 h2 = __floats2bfloat162_rn(b[j].x, b[j].y);
        __nv_bfloat162 h3 = __floats2bfloat162_rn(b[j].z, b[j].w);
        uint4 v;
        v.x = *(const uint32_t*)&h0; v.y = *(const uint32_t*)&h1;
        v.z = *(const uint32_t*)&h2; v.w = *(const uint32_t*)&h3;
        *(uint4*)(g_bf16 + (size_t)row * D + l * 8) = v;

        cs[0] += a[j].x; cs[1] += a[j].y; cs[2] += a[j].z; cs[3] += a[j].w;
        cs[4] += b[j].x; cs[5] += b[j].y; cs[6] += b[j].z; cs[7] += b[j].w;

        float sq = a[j].x * a[j].x + a[j].y * a[j].y + a[j].z * a[j].z + a[j].w * a[j].w
                 + b[j].x * b[j].x + b[j].y * b[j].y + b[j].z * b[j].z + b[j].w * b[j].w;
        #pragma unroll
        for (int k = 16; k; k >>= 1) sq += __shfl_xor_sync(0xFFFFFFFFu, sq, k);
        if (l == 0) { g_sq[row] = sq; swsq[w * 4 + j] = sq; }
    }

    *(float4*)&scol[w][l * 8]     = make_float4(cs[0], cs[1], cs[2], cs[3]);
    *(float4*)&scol[w][l * 8 + 4] = make_float4(cs[4], cs[5], cs[6], cs[7]);
    __syncthreads();

    float c = 0.f;
    #pragma unroll
    for (int i = 0; i < 8; i++) c += scol[i][t];
    atomicAdd(&g_colsum[t], c);
    if (t == 0) {
        double bs = 0.0;
        #pragma unroll
        for (int i = 0; i < 32; i++) bs += (double)swsq[i];
        atomicAdd(&g_sumsq, bs);
    }
}

// ---------------------------------------------------------------------------
// k_bw: bandwidth from sum(L2) = 2n*sumsq - 2*|colsum|^2  (1 block)
// ---------------------------------------------------------------------------
__global__ void k_bw() {
    __shared__ double red[256];
    int t = threadIdx.x;
    double c = (double)ldcg_f(&g_colsum[t]);
    red[t] = c * c;
    __syncthreads();
    #pragma unroll
    for (int s = 128; s > 0; s >>= 1) {
        if (t < s) red[t] += red[t + s];
        __syncthreads();
    }
    if (t == 0) {
        double n = (double)NROWS;
        double sumL2 = 2.0 * n * ldcg_d(&g_sumsq) - 2.0 * red[0];
        double bw = sumL2 / (n * n - n) * 0.25;   // / 2^(KERNEL_NUM//2)
        g_c2 = (float)(-1.0 / (16.0 * bw * 0.6931471805599453094));
    }
}

// ---------------------------------------------------------------------------
// k_mma: one upper-tri 128x128 tile pair per CTA.  (R12-proven, best measured)
//   Rolling mainloop with triple-buffer rotation (one sync per chunk):
//   stage(kc+1) writes buf (kc+1)%3, whose last reader was compute(kc-2) --
//   guaranteed finished because every warp issuing this stage passed the
//   barrier of iteration kc-1.
//   bf16 mma.sync, fp32 accum, packed-f32x2 exp epilogue, shuffle reduce,
//   one atomicAdd per CTA. 8 warps, warp tile = 32 (M) x 64 (N).
// ---------------------------------------------------------------------------
extern __shared__ char dynsmem[];

__global__ void __launch_bounds__(256, 2) k_mma() {
    __shared__ float  s_c2sqi[TILE];
    __shared__ float  s_c2sqj[TILE];
    __shared__ double sp8[8];

    const int t = threadIdx.x;
    const int w = t >> 5, l = t & 31;

    // decode upper-tri pair (I <= J)
    int I = 0, rem = blockIdx.x;
    while (rem >= NT - I) { rem -= NT - I; I++; }
    const int J = I + rem;

    const float c2 = g_c2;
    if (t < TILE) {
        s_c2sqi[t] = c2 * g_sq[I * TILE + t];
        s_c2sqj[t] = c2 * g_sq[J * TILE + t];
    }

    const __nv_bfloat16* Abase = g_bf16 + (size_t)I * TILE * D;
    const __nv_bfloat16* Bbase = g_bf16 + (size_t)J * TILE * D;
    const uint32_t sdyn = smem_u32(dynsmem);

    // ---- cp.async staging: 2048 x 16B chunks per K-chunk ----
    auto stage = [&](int kc, int buf) {
        #pragma unroll
        for (int i = 0; i < 8; i++) {
            int idx = t + i * 256;
            int op  = idx >> 10;
            int li  = idx & 1023;
            int row = li >> 3;
            int ch  = li & 7;
            const __nv_bfloat16* gp =
                (op ? Bbase : Abase) + (size_t)row * D + kc * BK + ch * 8;
            uint32_t dst = sdyn + (uint32_t)buf * BUFB + (uint32_t)op * ABYTES
                         + (uint32_t)(row * 128 + (((ch ^ (row & 7)) << 4)));
            cpasync16(dst, gp);
        }
        CP_COMMIT();
    };

    // ---- per-lane ldmatrix base offsets ----
    const int wm = (w >> 1) * 32;    // warp M offset (0,32,64,96)
    const int wn = (w & 1) * 64;     // warp N offset (0,64)
    const uint32_t xr   = (uint32_t)((l & 7) << 4);        // swizzle XOR
    const uint32_t arow = (uint32_t)(wm + (l & 15));
    const uint32_t khA  = (uint32_t)(l >> 4);
    const uint32_t brow = (uint32_t)(wn + (l & 7) + ((l & 16) ? 8 : 0));
    const uint32_t khB  = (uint32_t)((l >> 3) & 1);

    float acc[2][8][4];
    #pragma unroll
    for (int mi = 0; mi < 2; mi++)
        #pragma unroll
        for (int ni = 0; ni < 8; ni++)
            #pragma unroll
            for (int c = 0; c < 4; c++) acc[mi][ni][c] = 0.f;

    auto compute = [&](int buf) {
        const uint32_t bo = (uint32_t)buf * BUFB;
        const uint32_t aB = sdyn + bo + arow * 128u;
        const uint32_t bB = sdyn + bo + ABYTES + brow * 128u;
        #pragma unroll
        for (int kk = 0; kk < 4; kk++) {
            uint32_t ka = ((uint32_t)(kk * 32) + khA * 16u) ^ xr;
            uint32_t kb = ((uint32_t)(kk * 32) + khB * 16u) ^ xr;
            uint32_t af[2][4], bf[4][4];
            LDSM4(af[0], aB + ka);
            LDSM4(af[1], aB + 2048u + ka);
            LDSM4(bf[0], bB + kb);
            LDSM4(bf[1], bB + 2048u + kb);
            LDSM4(bf[2], bB + 4096u + kb);
            LDSM4(bf[3], bB + 6144u + kb);
            #pragma unroll
            for (int mi = 0; mi < 2; mi++)
                #pragma unroll
                for (int nj = 0; nj < 4; nj++) {
                    MMA16816(acc[mi][nj * 2 + 0], af[mi], bf[nj][0], bf[nj][1]);
                    MMA16816(acc[mi][nj * 2 + 1], af[mi], bf[nj][2], bf[nj][3]);
                }
        }
    };

    stage(0, 0);

    #pragma unroll 1
    for (int kc = 0; kc < NKC; kc++) {
        int nb = kc + 1;  if (nb >= NBUF) nb -= NBUF;   // (kc+1)%3
        if (kc + 1 < NKC) stage(kc + 1, nb);
        if (kc + 1 < NKC) { CP_WAIT(1); } else { CP_WAIT(0); }
        __syncthreads();
        int cb = kc;      if (cb >= NBUF) cb -= NBUF;   // kc%3
        compute(cb);
        // no trailing sync: next stage targets a buffer whose readers all
        // passed the previous iteration's barrier
    }

    // ---- fused epilogue ----
    // element (mi,ni,c): m = wm + mi*16 + gr + (c>=2)*8 ; n = wn + ni*8 + gc + (c&1)
    const int gr = l >> 2;
    const int gc = (l & 3) * 2;
    const float m2c2 = -2.0f * c2;
    const bool diag = (I == J);

    float facc = 0.f;
    if (!diag) {
        const uint64_t m2c2p = pk2(m2c2, m2c2);
        uint64_t rbp[2][2];
        #pragma unroll
        for (int mi = 0; mi < 2; mi++)
            #pragma unroll
            for (int rh = 0; rh < 2; rh++) {
                float rv = s_c2sqi[wm + mi * 16 + rh * 8 + gr];
                rbp[mi][rh] = pk2(rv, rv);
            }
        uint64_t cvp[8];
        #pragma unroll
        for (int ni = 0; ni < 8; ni++) {
            float c0 = s_c2sqj[wn + ni * 8 + gc];
            float c1 = s_c2sqj[wn + ni * 8 + gc + 1];
            cvp[ni] = pk2(c0, c1);
        }
        uint64_t faccp = pk2(0.f, 0.f);
        #pragma unroll
        for (int mi = 0; mi < 2; mi++)
            #pragma unroll
            for (int ni = 0; ni < 8; ni++)
                #pragma unroll
                for (int rh = 0; rh < 2; rh++) {
                    uint64_t accp = pk2(acc[mi][ni][rh * 2], acc[mi][ni][rh * 2 + 1]);
                    uint64_t argp = fma2p(accp, m2c2p, add2p(rbp[mi][rh], cvp[ni]));
                    float a0, a1; upk2(a0, a1, argp);
                    uint64_t u  = pk2(ex2f(a0), ex2f(a1));
                    uint64_t u2 = mul2p(u, u), u4 = mul2p(u2, u2);
                    uint64_t u8 = mul2p(u4, u4), u16 = mul2p(u8, u8);
                    uint64_t s  = add2p(add2p(u, u2), add2p(u4, u8));
                    faccp = add2p(faccp, add2p(s, u16));
                }
        float f0, f1; upk2(f0, f1, faccp);
        facc = f0 + f1;
    } else {
        float rb[2][2];
        #pragma unroll
        for (int mi = 0; mi < 2; mi++)
            #pragma unroll
            for (int rh = 0; rh < 2; rh++)
                rb[mi][rh] = s_c2sqi[wm + mi * 16 + rh * 8 + gr];
        #pragma unroll
        for (int mi = 0; mi < 2; mi++)
            #pragma unroll
            for (int ni = 0; ni < 8; ni++)
                #pragma unroll
                for (int c = 0; c < 4; c++) {
                    int rh = c >> 1, cc = c & 1;
                    int mm = wm + mi * 16 + rh * 8 + gr;
                    int nn = wn + ni * 8 + gc + cc;
                    float arg = fmaf(acc[mi][ni][c], m2c2,
                                     rb[mi][rh] + s_c2sqj[nn]);
                    float u = ex2f(arg);
                    float u2 = u * u, u4 = u2 * u2, u8 = u4 * u4, u16 = u8 * u8;
                    float kv = ((u + u2) + (u4 + u8)) + u16;
                    facc += (nn > mm) ? kv : 0.f;   // strict upper triangle
                }
    }

    // block reduction: warp shuffle in double, 8 partials, one atomic
    const double sg = ((I < NT / 2) == (J < NT / 2)) ? 1.0 : -1.0;
    double dv = (double)facc * sg;
    #pragma unroll
    for (int k = 16; k; k >>= 1) dv += __shfl_xor_sync(0xFFFFFFFFu, dv, k);
    if (l == 0) sp8[w] = dv;
    __syncthreads();
    if (t == 0) {
        double s = 0.0;
        #pragma unroll
        for (int i = 0; i < 8; i++) s += sp8[i];
        atomicAdd(&g_acc, s);
    }
}

// ---------------------------------------------------------------------------
// k_fin: result = (2*sum_{i<j} + 5*n) / b^2 (diagonal K_ii = 5 exactly);
// resets ALL accumulators for the next graph replay.
// ---------------------------------------------------------------------------
__global__ void k_fin(float* out) {
    int t = threadIdx.x;
    if (t == 0) {
        out[0] = (float)((2.0 * g_acc + 5.0 * (double)NROWS)
                         / ((double)B_ROWS * (double)B_ROWS));
        g_acc = 0.0;
        g_sumsq = 0.0;
    }
    g_colsum[t] = 0.f;
}

extern "C" void kernel_launch(void* const* d_in, const int* in_sizes, int n_in,
                              void* d_out, int out_size) {
    const float* src = (const float*)d_in[0];
    const float* tgt = (const float*)d_in[1];
    float* out = (float*)d_out;

    static const int kDynSmem = NBUF * BUFB;   // 96 KB triple-buffer rotation
    cudaFuncSetAttribute(k_mma, cudaFuncAttributeMaxDynamicSharedMemorySize, kDynSmem);

    k_prep<<<NROWS / 32, 256>>>(src, tgt);
    k_bw<<<1, 256>>>();
    k_mma<<<NPAIRS, 256, kDynSmem>>>();
    k_fin<<<1, 256>>>(out);
}